// round 16
// baseline (speedup 1.0000x reference)
#include <cuda_runtime.h>
#include <cstdint>
#include <math.h>

// Problem constants (match reference_code)
#define NUM_HINTS   32768
#define MAX_SUBSET  512
#define CHUNKS      5
#define NUM_ENTRIES 1000000

// Detected layout (written by repack_kernel block 0):
//   bit 0      : buffers swapped (A=mask, B=indices)
//   bits [1:3) : index encoding 0=int64-bits, 1=int32, 2=float64, 3=float32
//   bits [3:5) : mask elem width 0=1 byte, 1=4 bytes, 2=8 bytes
__device__ int g_cfg;

// Repacked entry table: 32B-aligned slot per entry:
//   words[0..4] = low-32 chunk words, words[5..7] = 0.
// 1e6 * 32B = 32 MB (sanctioned __device__ scratch). A gather touches exactly
// one 32B L2 sector and one 128B L1 line; a lane-pair's two 16B halves
// coalesce into a single L1 wavefront.
__device__ __align__(16) unsigned int g_padtab[NUM_ENTRIES * 8];

// ---------------- repack + (block 0 only) full layout detection --------------
// LESSON (R12/R13): per-block detect prologues multiply by ~28 block-waves;
// keep detect OUT of the 4096-block main kernel. It runs once here, in
// repack block 0, overlapped with repack's own work.
__global__ __launch_bounds__(256)
void repack_kernel(const void* __restrict__ E,
                   const unsigned char* __restrict__ A,
                   const unsigned char* __restrict__ B)
{
    const int t = threadIdx.x;

    // --- per-warp e64 detect: no shared mem, no __syncthreads ---
    // Raw int64 entries lie in [0,2^62): top 2 bits of EVERY u64 word zero.
    // int32-view entries have random top bits (all-64-pass prob ~4^-64).
    const int lane = t & 31;
    const unsigned long long* E8 = (const unsigned long long*)E;
    const bool ok = (E8[lane] >> 62) == 0ULL && (E8[lane + 32] >> 62) == 0ULL;
    const int e64 = __all_sync(0xFFFFFFFFu, ok) ? 1 : 0;

    // --- block 0: full cfg detection for the main kernel ---
    if (blockIdx.x == 0) {
        __shared__ int f[14];
        if (t < 14) f[t] = 1;
        __syncthreads();

        const unsigned long long* A8 = (const unsigned long long*)A;
        const unsigned long long* B8 = (const unsigned long long*)B;
        const unsigned int*       A4 = (const unsigned int*)A;
        const unsigned int*       B4 = (const unsigned int*)B;

        if (t < 64) {
            const unsigned long long va = A8[t], vb = B8[t];
            if (!(va == 0ULL || va == 1ULL || va == 0x3FF0000000000000ULL)) atomicAnd(&f[0], 0);
            if (!(vb == 0ULL || vb == 1ULL || vb == 0x3FF0000000000000ULL)) atomicAnd(&f[3], 0);
            const double da = __longlong_as_double((long long)va);
            const double db = __longlong_as_double((long long)vb);
            if (!(da >= 0.0 && da < 1.0e6 && da == floor(da))) atomicAnd(&f[6], 0);
            if (!(db >= 0.0 && db < 1.0e6 && db == floor(db))) atomicAnd(&f[10], 0);
            if (va >= (unsigned long long)NUM_ENTRIES) atomicAnd(&f[7], 0);
            if (vb >= (unsigned long long)NUM_ENTRIES) atomicAnd(&f[11], 0);
            const unsigned int wa = A4[t], wb = B4[t];
            if (!(wa == 0u || wa == 1u || wa == 0x3F800000u)) atomicAnd(&f[1], 0);
            if (!(wb == 0u || wb == 1u || wb == 0x3F800000u)) atomicAnd(&f[4], 0);
            if (wa >= (unsigned)NUM_ENTRIES) atomicAnd(&f[8], 0);
            if (wb >= (unsigned)NUM_ENTRIES) atomicAnd(&f[12], 0);
        }
        if (t < 128) {
            const float fa = __uint_as_float(A4[t]);
            const float fb = __uint_as_float(B4[t]);
            if (!(fa >= 0.0f && fa < 1.0e6f && fa == floorf(fa))) atomicAnd(&f[9], 0);
            if (!(fb >= 0.0f && fb < 1.0e6f && fb == floorf(fb))) atomicAnd(&f[13], 0);
        }
        if (A[t] > 1) atomicAnd(&f[2], 0);
        if (B[t] > 1) atomicAnd(&f[5], 0);
        __syncthreads();

        if (t == 0) {
            const int mwA = f[0] ? 2 : (f[1] ? 1 : (f[2] ? 0 : -1));
            const int mwB = f[3] ? 2 : (f[4] ? 1 : (f[5] ? 0 : -1));
            const int ieA = f[6] ? 2 : (f[7] ? 0 : (f[8] ? 1 : (f[9] ? 3 : -1)));
            const int ieB = f[10] ? 2 : (f[11] ? 0 : (f[12] ? 1 : (f[13] ? 3 : -1)));
            int swap, ie, mw;  // mask can alias index tests; never the reverse
            if      (mwB >= 0 && mwA < 0) { swap = 0; ie = (ieA >= 0 ? ieA : 0); mw = mwB; }
            else if (mwA >= 0 && mwB < 0) { swap = 1; ie = (ieB >= 0 ? ieB : 0); mw = mwA; }
            else                          { swap = 0; ie = (ieA >= 0 ? ieA : 0);
                                            mw = (mwB >= 0 ? mwB : 0); }
            g_cfg = swap | (ie << 1) | (mw << 3);
        }
    }

    // --- repack this thread's entry (source read once: evict-first) ---
    const int i = blockIdx.x * blockDim.x + t;
    if (i >= NUM_ENTRIES) return;

    unsigned int w0, w1, w2, w3, w4;
    if (e64) {
        const unsigned long long* p = (const unsigned long long*)E + (size_t)i * CHUNKS;
        w0 = (unsigned int)__ldcs(p + 0); w1 = (unsigned int)__ldcs(p + 1);
        w2 = (unsigned int)__ldcs(p + 2); w3 = (unsigned int)__ldcs(p + 3);
        w4 = (unsigned int)__ldcs(p + 4);
    } else {
        const unsigned int* p = (const unsigned int*)E + (size_t)i * CHUNKS;
        w0 = __ldcs(p + 0); w1 = __ldcs(p + 1); w2 = __ldcs(p + 2);
        w3 = __ldcs(p + 3); w4 = __ldcs(p + 4);
    }
    uint4* dst = reinterpret_cast<uint4*>(&g_padtab[(size_t)i * 8]);
    dst[0] = make_uint4(w0, w1, w2, w3);
    dst[1] = make_uint4(w4, 0u, 0u, 0u);
}

// ---------------- gather helper ----------------------------------------------

__device__ __forceinline__ void gather_xor(unsigned int idx, int half, uint4& acc)
{
    if (idx < (unsigned)NUM_ENTRIES) {
        const uint4 v = __ldg(reinterpret_cast<const uint4*>(
                                  &g_padtab[(size_t)idx * 8]) + half);
        acc.x ^= v.x; acc.y ^= v.y; acc.z ^= v.z; acc.w ^= v.w;
    }
}

// ---------------- fast path: int32 indices + 1-byte mask ---------------------
// Pair handles 4 CONSECUTIVE slots per step: one uint4 idx load + one uchar4
// mask load feed 4 predicated gathers. Cuts stream LDGs per warp from 64 to 16
// and stream wavefronts from 64 to 24. Outer unroll 2 bounds front-batched
// gathers to ~8 (R12 lesson: wider front-batching regresses via cross-CTA
// L1tex-queue spread).
__device__ __forceinline__ void accum_fast_i32_m1(
    const unsigned int* __restrict__ idx_row,
    const unsigned char* __restrict__ m_row,
    uint4& acc, const int pair, const int half)
{
    #pragma unroll 2
    for (int i = 0; i < MAX_SUBSET / 64; ++i) {
        const int s = 64 * i + 4 * pair;            // 16B-aligned
        const uint4  idx4 = __ldg(reinterpret_cast<const uint4*>(idx_row + s));
        const uchar4 m4   = __ldg(reinterpret_cast<const uchar4*>(m_row + s));
        if (m4.x) gather_xor(idx4.x, half, acc);
        if (m4.y) gather_xor(idx4.y, half, acc);
        if (m4.z) gather_xor(idx4.z, half, acc);
        if (m4.w) gather_xor(idx4.w, half, acc);
    }
}

// ---------------- generic fallback (other encodings) -------------------------
template <int IENC, typename MaskT>
__device__ __forceinline__ void accum_pair(
    const void* __restrict__ ibase,
    const MaskT* __restrict__ m_row,
    uint4& acc, const int pair, const int half)
{
    #pragma unroll 8
    for (int i = 0; i < MAX_SUBSET / 16; ++i) {
        const int s = 16 * i + pair;
        unsigned int idx;
        if (IENC == 0)      idx = (unsigned int)((const unsigned long long*)ibase)[s];
        else if (IENC == 1) idx = ((const unsigned int*)ibase)[s];
        else if (IENC == 2) idx = (unsigned int)(((const double*)ibase)[s]);
        else                idx = (unsigned int)(((const float*)ibase)[s]);
        const MaskT m = m_row[s];
        if (m) gather_xor(idx, half, acc);
    }
}

__global__ __launch_bounds__(256)
void hintgen_xor_kernel(const void* __restrict__ bufA,
                        const void* __restrict__ bufB,
                        float* __restrict__ out)
{
    const int cfg = g_cfg;                          // uniform broadcast load
    const void* I = (cfg & 1) ? bufB : bufA;
    const void* M = (cfg & 1) ? bufA : bufB;
    const int ie  = (cfg >> 1) & 3;
    const int mw  = (cfg >> 3) & 3;

    const unsigned int warp_global =
        blockIdx.x * (blockDim.x >> 5) + (threadIdx.x >> 5);
    const int lane = threadIdx.x & 31;
    const int pair = lane >> 1;
    const int half = lane & 1;

    const size_t row = (size_t)warp_global * MAX_SUBSET;
    uint4 acc = make_uint4(0u, 0u, 0u, 0u);

    if (ie == 1 && mw == 0) {
        // Fast path (the measured dataset layout): vectorized streams.
        accum_fast_i32_m1((const unsigned int*)I + row,
                          (const unsigned char*)M + row, acc, pair, half);
    } else {
        const void* I8 = (const unsigned char*)I + row * 8;   // i64-bits / f64
        const void* I4 = (const unsigned char*)I + row * 4;   // i32 / f32
        const unsigned char*      M1 = (const unsigned char*)M + row;
        const unsigned int*       M4 = (const unsigned int*)M + row;
        const unsigned long long* M8 = (const unsigned long long*)M + row;

        #define DISP_MW(IE, IROW)                                                  \
            if (mw == 0)      accum_pair<IE, unsigned char>(IROW, M1, acc, pair, half); \
            else if (mw == 1) accum_pair<IE, unsigned int>(IROW, M4, acc, pair, half);  \
            else              accum_pair<IE, unsigned long long>(IROW, M8, acc, pair, half);

        if (ie == 0)      { DISP_MW(0, I8) }
        else if (ie == 1) { DISP_MW(1, I4) }
        else if (ie == 2) { DISP_MW(2, I8) }
        else              { DISP_MW(3, I4) }
        #undef DISP_MW
    }

    // Parity-preserving butterfly: offsets 16,8,4,2 reduce within each lane
    // parity class. Lane 0 -> XOR of all even lanes (chunks 0-3),
    // lane 1 -> XOR of all odd lanes (chunk 4 in .x; .y/.z/.w stay 0).
    #pragma unroll
    for (int off = 16; off >= 2; off >>= 1) {
        acc.x ^= __shfl_xor_sync(0xFFFFFFFFu, acc.x, off);
        acc.y ^= __shfl_xor_sync(0xFFFFFFFFu, acc.y, off);
        acc.z ^= __shfl_xor_sync(0xFFFFFFFFu, acc.z, off);
        acc.w ^= __shfl_xor_sync(0xFFFFFFFFu, acc.w, off);
    }

    // d_out is float32; expected = f32(int32-wrapped parity). low32 of the
    // 64-bit XOR == XOR of low32 words, so 32-bit accumulators are exact.
    float* o = out + (size_t)warp_global * CHUNKS;
    if (lane == 0) {
        o[0] = (float)(int)acc.x;
        o[1] = (float)(int)acc.y;
        o[2] = (float)(int)acc.z;
        o[3] = (float)(int)acc.w;
    } else if (lane == 1) {
        o[4] = (float)(int)acc.x;
    }
}

extern "C" void kernel_launch(void* const* d_in, const int* in_sizes, int n_in,
                              void* d_out, int out_size)
{
    (void)out_size;
    // entries = input with the smallest element count (5M vs 16.7M),
    // robust to declared dtype width.
    int e = 0;
    if (n_in >= 3) {
        for (int k = 1; k < 3; ++k) if (in_sizes[k] < in_sizes[e]) e = k;
    }
    const void* entries = d_in[e];
    const void* bufA = d_in[(e == 0) ? 1 : 0];
    const void* bufB = d_in[(e == 2) ? 1 : 2];

    // repack_kernel also performs layout detection in block 0 (writes g_cfg),
    // hiding the former detect launch inside repack's runtime.
    repack_kernel<<<(NUM_ENTRIES + 255) / 256, 256>>>(
        entries, (const unsigned char*)bufA, (const unsigned char*)bufB);

    const int warps_per_block = 8;                   // 256 threads
    const int blocks = NUM_HINTS / warps_per_block;  // 4096
    hintgen_xor_kernel<<<blocks, warps_per_block * 32>>>(
        bufA, bufB, (float*)d_out);
}

// round 17
// speedup vs baseline: 1.6533x; 1.6533x over previous
#include <cuda_runtime.h>
#include <cstdint>
#include <math.h>

// Problem constants (match reference_code)
#define NUM_HINTS   32768
#define MAX_SUBSET  512
#define CHUNKS      5
#define NUM_ENTRIES 1000000

// Detected layout (written by repack_kernel block 0):
//   bit 0      : buffers swapped (A=mask, B=indices)
//   bits [1:3) : index encoding 0=int64-bits, 1=int32, 2=float64, 3=float32
//   bits [3:5) : mask elem width 0=1 byte, 1=4 bytes, 2=8 bytes
__device__ int g_cfg;

// Repacked entry table: 32B-aligned slot per entry:
//   words[0..4] = low-32 chunk words, words[5..7] = 0.
// 1e6 * 32B = 32 MB (sanctioned __device__ scratch). A gather touches exactly
// one 32B L2 sector and one 128B L1 line; a lane-pair's two 16B halves
// coalesce into a single L1 wavefront.
__device__ __align__(16) unsigned int g_padtab[NUM_ENTRIES * 8];

// ---------------- repack + (block 0 only) full layout detection --------------
// LESSON (R12/R13): per-block detect prologues multiply by ~28 block-waves;
// keep detect OUT of the 4096-block main kernel. It runs once here, in
// repack block 0, overlapped with repack's own work.
__global__ __launch_bounds__(256)
void repack_kernel(const void* __restrict__ E,
                   const unsigned char* __restrict__ A,
                   const unsigned char* __restrict__ B)
{
    const int t = threadIdx.x;

    // --- per-warp e64 detect: no shared mem, no __syncthreads ---
    // Raw int64 entries lie in [0,2^62): top 2 bits of EVERY u64 word zero.
    // int32-view entries have random top bits (all-64-pass prob ~4^-64).
    const int lane = t & 31;
    const unsigned long long* E8 = (const unsigned long long*)E;
    const bool ok = (E8[lane] >> 62) == 0ULL && (E8[lane + 32] >> 62) == 0ULL;
    const int e64 = __all_sync(0xFFFFFFFFu, ok) ? 1 : 0;

    // --- block 0: full cfg detection for the main kernel ---
    if (blockIdx.x == 0) {
        __shared__ int f[14];
        if (t < 14) f[t] = 1;
        __syncthreads();

        const unsigned long long* A8 = (const unsigned long long*)A;
        const unsigned long long* B8 = (const unsigned long long*)B;
        const unsigned int*       A4 = (const unsigned int*)A;
        const unsigned int*       B4 = (const unsigned int*)B;

        if (t < 64) {
            const unsigned long long va = A8[t], vb = B8[t];
            if (!(va == 0ULL || va == 1ULL || va == 0x3FF0000000000000ULL)) atomicAnd(&f[0], 0);
            if (!(vb == 0ULL || vb == 1ULL || vb == 0x3FF0000000000000ULL)) atomicAnd(&f[3], 0);
            const double da = __longlong_as_double((long long)va);
            const double db = __longlong_as_double((long long)vb);
            if (!(da >= 0.0 && da < 1.0e6 && da == floor(da))) atomicAnd(&f[6], 0);
            if (!(db >= 0.0 && db < 1.0e6 && db == floor(db))) atomicAnd(&f[10], 0);
            if (va >= (unsigned long long)NUM_ENTRIES) atomicAnd(&f[7], 0);
            if (vb >= (unsigned long long)NUM_ENTRIES) atomicAnd(&f[11], 0);
            const unsigned int wa = A4[t], wb = B4[t];
            if (!(wa == 0u || wa == 1u || wa == 0x3F800000u)) atomicAnd(&f[1], 0);
            if (!(wb == 0u || wb == 1u || wb == 0x3F800000u)) atomicAnd(&f[4], 0);
            if (wa >= (unsigned)NUM_ENTRIES) atomicAnd(&f[8], 0);
            if (wb >= (unsigned)NUM_ENTRIES) atomicAnd(&f[12], 0);
        }
        if (t < 128) {
            const float fa = __uint_as_float(A4[t]);
            const float fb = __uint_as_float(B4[t]);
            if (!(fa >= 0.0f && fa < 1.0e6f && fa == floorf(fa))) atomicAnd(&f[9], 0);
            if (!(fb >= 0.0f && fb < 1.0e6f && fb == floorf(fb))) atomicAnd(&f[13], 0);
        }
        if (A[t] > 1) atomicAnd(&f[2], 0);
        if (B[t] > 1) atomicAnd(&f[5], 0);
        __syncthreads();

        if (t == 0) {
            const int mwA = f[0] ? 2 : (f[1] ? 1 : (f[2] ? 0 : -1));
            const int mwB = f[3] ? 2 : (f[4] ? 1 : (f[5] ? 0 : -1));
            const int ieA = f[6] ? 2 : (f[7] ? 0 : (f[8] ? 1 : (f[9] ? 3 : -1)));
            const int ieB = f[10] ? 2 : (f[11] ? 0 : (f[12] ? 1 : (f[13] ? 3 : -1)));
            int swap, ie, mw;  // mask can alias index tests; never the reverse
            if      (mwB >= 0 && mwA < 0) { swap = 0; ie = (ieA >= 0 ? ieA : 0); mw = mwB; }
            else if (mwA >= 0 && mwB < 0) { swap = 1; ie = (ieB >= 0 ? ieB : 0); mw = mwA; }
            else                          { swap = 0; ie = (ieA >= 0 ? ieA : 0);
                                            mw = (mwB >= 0 ? mwB : 0); }
            g_cfg = swap | (ie << 1) | (mw << 3);
        }
    }

    // --- repack this thread's entry (source read once: evict-first) ---
    const int i = blockIdx.x * blockDim.x + t;
    if (i >= NUM_ENTRIES) return;

    unsigned int w0, w1, w2, w3, w4;
    if (e64) {
        const unsigned long long* p = (const unsigned long long*)E + (size_t)i * CHUNKS;
        w0 = (unsigned int)__ldcs(p + 0); w1 = (unsigned int)__ldcs(p + 1);
        w2 = (unsigned int)__ldcs(p + 2); w3 = (unsigned int)__ldcs(p + 3);
        w4 = (unsigned int)__ldcs(p + 4);
    } else {
        const unsigned int* p = (const unsigned int*)E + (size_t)i * CHUNKS;
        w0 = __ldcs(p + 0); w1 = __ldcs(p + 1); w2 = __ldcs(p + 2);
        w3 = __ldcs(p + 3); w4 = __ldcs(p + 4);
    }
    uint4* dst = reinterpret_cast<uint4*>(&g_padtab[(size_t)i * 8]);
    dst[0] = make_uint4(w0, w1, w2, w3);
    dst[1] = make_uint4(w4, 0u, 0u, 0u);
}

// ---------------- hot path: pair-cooperative gather --------------------------
// R14 measured-fastest loop shape: flat body, ONE combined if per gather,
// independent iterations, unroll 8, single accumulator chain. LESSONS:
//  - R12/R16: widening/branch-splitting the body collapses front-batched MLP
//    or oversubscribes the L1tex queue. Do not restructure this loop.
//  - R15: __ldcs on these stream loads regressed; keep default loads.
// NEW (R17): min-blocks 8 in __launch_bounds__ caps regs at 32 -> 64 resident
// warps/SM (occ 66.8% -> ~100%) to hide more of the ~250cyc L2-hit gather
// latency that holds the kernel 15us above its wavefront floor.
template <int IENC, typename MaskT>
__device__ __forceinline__ void accum_pair(
    const void* __restrict__ ibase,
    const MaskT* __restrict__ m_row,
    uint4& acc, const int pair, const int half)
{
    #pragma unroll 8
    for (int i = 0; i < MAX_SUBSET / 16; ++i) {
        const int s = 16 * i + pair;
        unsigned int idx;
        if (IENC == 0)      idx = (unsigned int)((const unsigned long long*)ibase)[s];
        else if (IENC == 1) idx = ((const unsigned int*)ibase)[s];
        else if (IENC == 2) idx = (unsigned int)(((const double*)ibase)[s]);
        else                idx = (unsigned int)(((const float*)ibase)[s]);
        const MaskT m = m_row[s];
        if (m && idx < (unsigned)NUM_ENTRIES) {     // uniform within the pair
            const uint4 v = __ldg(reinterpret_cast<const uint4*>(
                                      &g_padtab[(size_t)idx * 8]) + half);
            acc.x ^= v.x; acc.y ^= v.y; acc.z ^= v.z; acc.w ^= v.w;
        }
    }
}

__global__ __launch_bounds__(256, 8)
void hintgen_xor_kernel(const void* __restrict__ bufA,
                        const void* __restrict__ bufB,
                        float* __restrict__ out)
{
    const int cfg = g_cfg;                          // uniform broadcast load
    const void* I = (cfg & 1) ? bufB : bufA;
    const void* M = (cfg & 1) ? bufA : bufB;
    const int ie  = (cfg >> 1) & 3;
    const int mw  = (cfg >> 3) & 3;

    const unsigned int warp_global =
        blockIdx.x * (blockDim.x >> 5) + (threadIdx.x >> 5);
    const int lane = threadIdx.x & 31;
    const int pair = lane >> 1;
    const int half = lane & 1;

    const size_t row = (size_t)warp_global * MAX_SUBSET;
    uint4 acc = make_uint4(0u, 0u, 0u, 0u);

    const void* I8 = (const unsigned char*)I + row * 8;   // i64-bits / f64
    const void* I4 = (const unsigned char*)I + row * 4;   // i32 / f32
    const unsigned char*      M1 = (const unsigned char*)M + row;
    const unsigned int*       M4 = (const unsigned int*)M + row;
    const unsigned long long* M8 = (const unsigned long long*)M + row;

    #define DISP_MW(IE, IROW)                                                  \
        if (mw == 0)      accum_pair<IE, unsigned char>(IROW, M1, acc, pair, half); \
        else if (mw == 1) accum_pair<IE, unsigned int>(IROW, M4, acc, pair, half);  \
        else              accum_pair<IE, unsigned long long>(IROW, M8, acc, pair, half);

    if (ie == 0)      { DISP_MW(0, I8) }
    else if (ie == 1) { DISP_MW(1, I4) }
    else if (ie == 2) { DISP_MW(2, I8) }
    else              { DISP_MW(3, I4) }
    #undef DISP_MW

    // Parity-preserving butterfly: offsets 16,8,4,2 reduce within each lane
    // parity class. Lane 0 -> XOR of all even lanes (chunks 0-3),
    // lane 1 -> XOR of all odd lanes (chunk 4 in .x; .y/.z/.w stay 0).
    #pragma unroll
    for (int off = 16; off >= 2; off >>= 1) {
        acc.x ^= __shfl_xor_sync(0xFFFFFFFFu, acc.x, off);
        acc.y ^= __shfl_xor_sync(0xFFFFFFFFu, acc.y, off);
        acc.z ^= __shfl_xor_sync(0xFFFFFFFFu, acc.z, off);
        acc.w ^= __shfl_xor_sync(0xFFFFFFFFu, acc.w, off);
    }

    // d_out is float32; expected = f32(int32-wrapped parity). low32 of the
    // 64-bit XOR == XOR of low32 words, so 32-bit accumulators are exact.
    float* o = out + (size_t)warp_global * CHUNKS;
    if (lane == 0) {
        o[0] = (float)(int)acc.x;
        o[1] = (float)(int)acc.y;
        o[2] = (float)(int)acc.z;
        o[3] = (float)(int)acc.w;
    } else if (lane == 1) {
        o[4] = (float)(int)acc.x;
    }
}

extern "C" void kernel_launch(void* const* d_in, const int* in_sizes, int n_in,
                              void* d_out, int out_size)
{
    (void)out_size;
    // entries = input with the smallest element count (5M vs 16.7M),
    // robust to declared dtype width.
    int e = 0;
    if (n_in >= 3) {
        for (int k = 1; k < 3; ++k) if (in_sizes[k] < in_sizes[e]) e = k;
    }
    const void* entries = d_in[e];
    const void* bufA = d_in[(e == 0) ? 1 : 0];
    const void* bufB = d_in[(e == 2) ? 1 : 2];

    // repack_kernel also performs layout detection in block 0 (writes g_cfg),
    // hiding the former detect launch inside repack's runtime.
    repack_kernel<<<(NUM_ENTRIES + 255) / 256, 256>>>(
        entries, (const unsigned char*)bufA, (const unsigned char*)bufB);

    const int warps_per_block = 8;                   // 256 threads
    const int blocks = NUM_HINTS / warps_per_block;  // 4096
    hintgen_xor_kernel<<<blocks, warps_per_block * 32>>>(
        bufA, bufB, (float*)d_out);
}